// round 11
// baseline (speedup 1.0000x reference)
#include <cuda_runtime.h>
#include <cstdint>

// Problem constants
#define NPROB 2048      // B*S = 8*256
#define DD    128       // feature dim (m = n = 128)
#define NITER 20
#define NB    128       // LUT bins

// K = (SCALE/eps) * log2(e) = 3000 * log2(e)
#define KCOEF 4328.085098989891f
#define TWOK  8656.170197979782f
#define INVK  2.3105011120474482e-4f
// ot scale: n * SCALE / NPROB = 128*300/2048
#define OTSCALE 18.75f

#define NCOPY   32
#define TH_SKIP 34.0f            // keep terms within 2^-34 of true max
#define PLAN_TH -35.0f           // plan entries below 2^-35 dropped
#define E_TH    -39.0f
#define CTOL    1.0e-5f          // convergence tol (log2 units)
#define FIX_SCALE 1099511627776.0f // 2^40 fixed-point scale

__device__ unsigned long long g_accum[(size_t)NCOPY * DD * DD];
__device__ float g_ot[DD * DD];

__device__ __forceinline__ float ex2f(float x) {
    float r; asm("ex2.approx.ftz.f32 %0, %1;" : "=f"(r) : "f"(x)); return r;
}
__device__ __forceinline__ float lg2f(float x) {
    float r; asm("lg2.approx.f32 %0, %1;" : "=f"(r) : "f"(x)); return r;
}
__device__ __forceinline__ float warp_max(float v) {
#pragma unroll
    for (int o = 16; o; o >>= 1) v = fmaxf(v, __shfl_xor_sync(0xffffffffu, v, o));
    return v;
}

// Full two-pass LSE sweep (safety net only; should never fire).
__device__ __forceinline__ float lse_full(const float2* __restrict__ arr, float twoKc) {
    const float4* a4 = reinterpret_cast<const float4*>(arr);
    float m0 = -1e30f, m1 = -1e30f, m2 = -1e30f, m3 = -1e30f;
#pragma unroll 8
    for (int q = 0; q < DD / 4; ++q) {
        float4 u = a4[2 * q];
        float4 w = a4[2 * q + 1];
        m0 = fmaxf(m0, fmaf(twoKc, u.x, u.y));
        m1 = fmaxf(m1, fmaf(twoKc, u.z, u.w));
        m2 = fmaxf(m2, fmaf(twoKc, w.x, w.y));
        m3 = fmaxf(m3, fmaf(twoKc, w.z, w.w));
    }
    float mx = fmaxf(fmaxf(m0, m1), fmaxf(m2, m3));
    float s0 = 0.f, s1 = 0.f, s2 = 0.f, s3 = 0.f;
#pragma unroll 8
    for (int q = 0; q < DD / 4; ++q) {
        float4 u = a4[2 * q];
        float4 w = a4[2 * q + 1];
        s0 += ex2f(fmaf(twoKc, u.x, u.y) - mx);
        s1 += ex2f(fmaf(twoKc, u.z, u.w) - mx);
        s2 += ex2f(fmaf(twoKc, w.x, w.y) - mx);
        s3 += ex2f(fmaf(twoKc, w.z, w.w) - mx);
    }
    float s = (s0 + s1) + (s2 + s3);
    return -(7.0f + mx + lg2f(s));
}

// Element window [lo,hi] -> element index range via bin LUT (O(1), 2 LDS).
// LUT[q] = #keys < kmin + q*w; widened by 1 bin each side for rounding safety.
// Over-inclusion is harmless: every element is a legitimate LSE term.
__device__ __forceinline__ void lut_range(const int* __restrict__ lut,
                                          float kmin, float invw,
                                          float lo, float hi,
                                          int& jlo, int& jhi) {
    int bl = __float2int_rd((lo - kmin) * invw) - 1;
    bl = bl < 0 ? 0 : (bl > NB ? NB : bl);
    int bh = __float2int_rd((hi - kmin) * invw) + 2;
    bh = bh < 0 ? 0 : (bh > NB ? NB : bh);
    jlo = lut[bl];
    jhi = lut[bh];
}

// One-pass windowed LSE with a NEVER-STALE shift:
//   v* = value of the LUT-nearest element (current potentials) -> valid lower bound
//   on the true max, and that element is provably inside the window, so
//   s = sum 2^(v - v*) >= 1 at EVERY iteration. No stale estimate, no full sweep.
__device__ __forceinline__ float lse_onepass(const float2* __restrict__ arr,
                                             const int* __restrict__ lut,
                                             float kmin, float invw,
                                             float c, float twoKc, float wmax,
                                             bool* bad) {
    // nearest element via bin LUT (clamped; any element is a valid lower bound)
    int jb = __float2int_rd((c - kmin) * invw);
    jb = jb < 0 ? 0 : (jb > NB - 1 ? NB - 1 : jb);
    int js = lut[jb];
    js = js > DD - 1 ? DD - 1 : js;
    float2 es = arr[js];
    float vst = fmaf(twoKc, es.x, es.y);
    // window radius: r2 = c^2 + (wmax + TH - v*)/K; contains j* by construction
    float r2 = fmaf(c, c, (wmax + TH_SKIP - vst) * INVK);
    float r = sqrtf(fmaxf(r2, 0.f));
    float lo = c - r, hi = c + r;
#pragma unroll
    for (int o = 1; o <= 4; o <<= 1) {          // 8-lane union
        lo = fminf(lo, __shfl_xor_sync(0xffffffffu, lo, o));
        hi = fmaxf(hi, __shfl_xor_sync(0xffffffffu, hi, o));
    }
    int jlo, jhi;
    lut_range(lut, kmin, invw, lo, hi, jlo, jhi);
    int G0 = jlo >> 2, G1 = (jhi + 3) >> 2;
    const float4* a4 = reinterpret_cast<const float4*>(arr);
    float s0 = 0.f, s1 = 0.f;
    for (int g = G0; g < G1; ++g) {             // uniform, branch-free
        float4 u = a4[2 * g];
        float4 w = a4[2 * g + 1];
        s0 += ex2f(fmaf(twoKc, u.x, u.y) - vst);
        s1 += ex2f(fmaf(twoKc, u.z, u.w) - vst);
        s0 += ex2f(fmaf(twoKc, w.x, w.y) - vst);
        s1 += ex2f(fmaf(twoKc, w.z, w.w) - vst);
    }
    float s = s0 + s1;
    *bad = !(s >= 0.999f && s <= 1e30f);        // overflow-only guard; ~never fires
    return -(7.0f + vst + lg2f(s));
}

__global__ void __launch_bounds__(128) sinkhorn_kernel(const float* __restrict__ X,
                                                       const float* __restrict__ Y) {
    __shared__ __align__(16) float2 sx[DD];   // {sorted x, pot a}
    __shared__ __align__(16) float2 sy[DD];   // {sorted y, pot b}
    __shared__ int ox[DD], oy[DD];            // original indices
    __shared__ __align__(16) float kx[DD], ky[DD];   // sorted coords
    __shared__ int lutx[NB + 1], luty[NB + 1];
    __shared__ float wxp[4], wyp[4];          // per-warp maxes of w = pot + K*coord^2
    __shared__ float sc[4];                   // kminx, invwx, kminy, invwy

    const int p = blockIdx.x;
    const int t = threadIdx.x;

    kx[t] = X[(size_t)p * DD + t]; ox[t] = t;
    ky[t] = Y[(size_t)p * DD + t]; oy[t] = t;
    if (t < 4) { wxp[t] = 0.f; wyp[t] = 0.f; }   // w == 0 at init
    __syncthreads();

    // Bitonic sort both (kx,ox) and (ky,oy) ascending; index tiebreak.
    for (int k = 2; k <= DD; k <<= 1) {
        for (int j = k >> 1; j > 0; j >>= 1) {
            int prt = t ^ j;
            bool keep_small = ((t < prt) == ((t & k) == 0));
            float mkx = kx[t], pkx = kx[prt];
            int   mix = ox[t], pix = ox[prt];
            float mky = ky[t], pky = ky[prt];
            int   miy = oy[t], piy = oy[prt];
            __syncthreads();
            bool lessx = (mkx < pkx) || (mkx == pkx && mix < pix);
            bool takex = (lessx == keep_small);
            kx[t] = takex ? mkx : pkx;  ox[t] = takex ? mix : pix;
            bool lessy = (mky < pky) || (mky == pky && miy < piy);
            bool takey = (lessy == keep_small);
            ky[t] = takey ? mky : pky;  oy[t] = takey ? miy : piy;
            __syncthreads();
        }
    }

    // Build bin LUTs (once). Bin widths from sorted extremes.
    if (t == 0) {
        sc[0] = kx[0];  sc[1] = (float)NB / (kx[DD - 1] - kx[0]);
        sc[2] = ky[0];  sc[3] = (float)NB / (ky[DD - 1] - ky[0]);
        lutx[NB] = DD;  luty[NB] = DD;
    }
    __syncthreads();
    {
        float wx = 1.0f / sc[1], wy = 1.0f / sc[3];
        float bx = sc[0] + (float)t * wx;
        float by = sc[2] + (float)t * wy;
        int cx = 0, cy = 0;
#pragma unroll
        for (int st = 128; st; st >>= 1) {
            int c = cx + st;
            if (c <= DD && kx[c - 1] < bx) cx = c;
            int c2 = cy + st;
            if (c2 <= DD && ky[c2 - 1] < by) cy = c2;
        }
        lutx[t] = cx;
        luty[t] = cy;
    }

    const float x = kx[t];
    const float y = ky[t];
    const float twoKx = TWOK * x;
    const float twoKy = TWOK * y;
    const float Kx2 = KCOEF * x * x;
    const float Ky2 = KCOEF * y * y;
    float areg = -Kx2;
    float breg = -Ky2;
    sx[t] = make_float2(x, areg);
    sy[t] = make_float2(y, breg);
    __syncthreads();

    const float kminy = sc[2], invwy = sc[3];
    const float kminx = sc[0], invwx = sc[1];

    for (int it = 0; it < NITER; ++it) {
        // ---- f-update (rows; reduce over sy) ----
        float wmaxy = fmaxf(fmaxf(wyp[0], wyp[1]), fmaxf(wyp[2], wyp[3]));
        bool bad;
        float a_new = lse_onepass(sy, luty, kminy, invwy, x, twoKx, wmaxy, &bad);
        if (__any_sync(0xffffffffu, bad)) a_new = lse_full(sy, twoKx);
        float amov = fabsf(a_new - areg);
        areg = a_new;
        sx[t].y = a_new;
        float wm = warp_max(a_new + Kx2);
        if ((t & 31) == 0) wxp[t >> 5] = wm;
        __syncthreads();

        // ---- g-update (cols; reduce over sx) ----
        float wmaxx = fmaxf(fmaxf(wxp[0], wxp[1]), fmaxf(wxp[2], wxp[3]));
        float b_new = lse_onepass(sx, lutx, kminx, invwx, y, twoKy, wmaxx, &bad);
        if (__any_sync(0xffffffffu, bad)) b_new = lse_full(sx, twoKy);
        float bmov = fabsf(b_new - breg);
        breg = b_new;
        sy[t].y = b_new;
        float wn = warp_max(b_new + Ky2);
        if ((t & 31) == 0) wyp[t >> 5] = wn;

        int moved = (amov > CTOL) || (bmov > CTOL);
        if (!__syncthreads_or(moved)) break;
    }

    // ---- Plan accumulation: thread t = sorted row t; fixed-point atomic adds ----
    {
        const int oi = ox[t];
        unsigned long long* rowp =
            g_accum + (size_t)(p & (NCOPY - 1)) * (DD * DD) + (size_t)oi * DD;
        float wmaxy = fmaxf(fmaxf(wyp[0], wyp[1]), fmaxf(wyp[2], wyp[3]));
        float r2 = fmaf(x, x, (wmaxy + areg - PLAN_TH) * INVK);
        float r = sqrtf(fmaxf(r2, 0.f));
        float lo = x - r, hi = x + r;
#pragma unroll
        for (int o = 1; o <= 4; o <<= 1) {
            lo = fminf(lo, __shfl_xor_sync(0xffffffffu, lo, o));
            hi = fmaxf(hi, __shfl_xor_sync(0xffffffffu, hi, o));
        }
        int jlo, jhi;
        lut_range(luty, kminy, invwy, lo, hi, jlo, jhi);
        int G0 = jlo >> 2, G1 = (jhi + 3) >> 2;
        const float4* a4 = reinterpret_cast<const float4*>(sy);
        for (int g = G0; g < G1; ++g) {
            float4 u = a4[2 * g];
            float4 w = a4[2 * g + 1];
            float E0 = fmaf(twoKx, u.x, u.y) + areg;
            float E1 = fmaf(twoKx, u.z, u.w) + areg;
            float E2 = fmaf(twoKx, w.x, w.y) + areg;
            float E3 = fmaf(twoKx, w.z, w.w) + areg;
            if (E0 > E_TH)
                atomicAdd(rowp + oy[4 * g + 0], __float2ull_rn(ex2f(E0) * FIX_SCALE));
            if (E1 > E_TH)
                atomicAdd(rowp + oy[4 * g + 1], __float2ull_rn(ex2f(E1) * FIX_SCALE));
            if (E2 > E_TH)
                atomicAdd(rowp + oy[4 * g + 2], __float2ull_rn(ex2f(E2) * FIX_SCALE));
            if (E3 > E_TH)
                atomicAdd(rowp + oy[4 * g + 3], __float2ull_rn(ex2f(E3) * FIX_SCALE));
        }
    }
}

__global__ void __launch_bounds__(256) zero_accum_kernel() {
    const int idx = blockIdx.x * 256 + threadIdx.x;
    g_accum[idx] = 0ull;
}

// Sum 32 fixed-point copies (exact integer sum -> deterministic), scale, add delta.
__global__ void __launch_bounds__(256) reduce_b_kernel(const float* __restrict__ delta) {
    const int idx = blockIdx.x * 256 + threadIdx.x;
    unsigned long long tot = 0ull;
#pragma unroll
    for (int c = 0; c < NCOPY; ++c) tot += g_accum[(size_t)c * (DD * DD) + idx];
    g_ot[idx] = (float)((double)tot * ((double)OTSCALE / (double)FIX_SCALE)) + delta[idx];
}

// out[p, :] = X[p, :] @ ot  -- measured-best config (11.0us, occ 78%).
__global__ void __launch_bounds__(128) gemm_out_kernel(const float* __restrict__ X,
                                                       float* __restrict__ out) {
    __shared__ float xs[DD];
    const int p = blockIdx.x;
    const int t = threadIdx.x;
    xs[t] = X[(size_t)p * DD + t];
    __syncthreads();
    float a0 = 0.f, a1 = 0.f, a2 = 0.f, a3 = 0.f;
#pragma unroll 8
    for (int i = 0; i < DD; i += 4) {
        a0 = fmaf(xs[i + 0], g_ot[(i + 0) * DD + t], a0);
        a1 = fmaf(xs[i + 1], g_ot[(i + 1) * DD + t], a1);
        a2 = fmaf(xs[i + 2], g_ot[(i + 2) * DD + t], a2);
        a3 = fmaf(xs[i + 3], g_ot[(i + 3) * DD + t], a3);
    }
    out[(size_t)p * DD + t] = (a0 + a1) + (a2 + a3);
}

extern "C" void kernel_launch(void* const* d_in, const int* in_sizes, int n_in,
                              void* d_out, int out_size) {
    const float* X = (const float*)d_in[0];      // [8,256,128]
    const float* Y = (const float*)d_in[1];      // [8,256,128]
    const float* delta = (const float*)d_in[2];  // [128,128]
    float* out = (float*)d_out;                  // [8,256,128] float32

    zero_accum_kernel<<<(NCOPY * DD * DD) / 256, 256>>>();
    sinkhorn_kernel<<<NPROB, 128>>>(X, Y);
    reduce_b_kernel<<<(DD * DD) / 256, 256>>>(delta);
    gemm_out_kernel<<<NPROB, 128>>>(X, out);
}

// round 13
// speedup vs baseline: 1.5683x; 1.5683x over previous
#include <cuda_runtime.h>
#include <cstdint>

// Problem constants
#define NPROB 2048      // B*S = 8*256
#define DD    128       // feature dim (m = n = 128)
#define NITER 20

// K = (SCALE/eps) * log2(e) = 3000 * log2(e)
#define KCOEF 4328.085098989891f
#define TWOK  8656.170197979782f
#define INVK  2.3105011120474482e-4f
// ot scale: n * SCALE / NPROB = 128*300/2048
#define OTSCALE 18.75f

#define NCOPY   32
#define TH_SKIP 34.0f            // keep terms within 2^-34 of shift-relative max
#define SMIN    2.44140625e-4f   // 2^-12: below this the window may clip real mass
#define SMAXB   1.0e30f          // overflow-only upper guard (large s is accurate)
#define PLAN_TH 35.0f            // plan keep threshold: E >= -35
#define E_TH    -39.0f
#define CTOL    1.0e-5f          // convergence tol (log2 units)
#define FIX_SCALE 1099511627776.0f // 2^40 fixed-point scale

__device__ unsigned long long g_accum[(size_t)NCOPY * DD * DD];
__device__ float g_ot[DD * DD];

__device__ __forceinline__ float ex2f(float x) {
    float r; asm("ex2.approx.ftz.f32 %0, %1;" : "=f"(r) : "f"(x)); return r;
}
__device__ __forceinline__ float lg2f(float x) {
    float r; asm("lg2.approx.f32 %0, %1;" : "=f"(r) : "f"(x)); return r;
}
__device__ __forceinline__ float warp_max(float v) {
#pragma unroll
    for (int o = 16; o; o >>= 1) v = fmaxf(v, __shfl_xor_sync(0xffffffffu, v, o));
    return v;
}

// Full two-pass LSE sweep (it=0 + rare guard fallback; warp-uniform call).
__device__ __forceinline__ float lse_full(const float2* __restrict__ arr, float twoKc) {
    const float4* a4 = reinterpret_cast<const float4*>(arr);
    float m0 = -1e30f, m1 = -1e30f, m2 = -1e30f, m3 = -1e30f;
#pragma unroll 8
    for (int q = 0; q < DD / 4; ++q) {
        float4 u = a4[2 * q];
        float4 w = a4[2 * q + 1];
        m0 = fmaxf(m0, fmaf(twoKc, u.x, u.y));
        m1 = fmaxf(m1, fmaf(twoKc, u.z, u.w));
        m2 = fmaxf(m2, fmaf(twoKc, w.x, w.y));
        m3 = fmaxf(m3, fmaf(twoKc, w.z, w.w));
    }
    float mx = fmaxf(fmaxf(m0, m1), fmaxf(m2, m3));
    float s0 = 0.f, s1 = 0.f, s2 = 0.f, s3 = 0.f;
#pragma unroll 8
    for (int q = 0; q < DD / 4; ++q) {
        float4 u = a4[2 * q];
        float4 w = a4[2 * q + 1];
        s0 += ex2f(fmaf(twoKc, u.x, u.y) - mx);
        s1 += ex2f(fmaf(twoKc, u.z, u.w) - mx);
        s2 += ex2f(fmaf(twoKc, w.x, w.y) - mx);
        s3 += ex2f(fmaf(twoKc, w.z, w.w) - mx);
    }
    float s = (s0 + s1) + (s2 + s3);
    return -(7.0f + mx + lg2f(s));
}

__global__ void __launch_bounds__(128) sinkhorn_kernel(const float* __restrict__ X,
                                                       const float* __restrict__ Y) {
    __shared__ __align__(16) float2 sx[DD];   // {sorted x, pot a}
    __shared__ __align__(16) float2 sy[DD];   // {sorted y, pot b}
    __shared__ int ox[DD], oy[DD];            // original indices
    __shared__ __align__(16) float kx[DD], ky[DD];   // sorted coords
    __shared__ float apw[32], bpw[32];        // per-group max of w = pot + K*coord^2
    __shared__ float xgl[32], xgh[32], ygl[32], ygh[32];  // group coord extremes
    __shared__ float wxl[4], wxh[4], wyl[4], wyh[4];      // warp coord extremes
    __shared__ float wxp[4], wyp[4];          // per-warp max of w (current side)

    const int p = blockIdx.x;
    const int t = threadIdx.x;
    const int myw = t >> 5;
    const int lane = t & 31;

    kx[t] = X[(size_t)p * DD + t]; ox[t] = t;
    ky[t] = Y[(size_t)p * DD + t]; oy[t] = t;
    __syncthreads();

    // Bitonic sort both (kx,ox) and (ky,oy) ascending; index tiebreak.
    for (int k = 2; k <= DD; k <<= 1) {
        for (int j = k >> 1; j > 0; j >>= 1) {
            int prt = t ^ j;
            bool keep_small = ((t < prt) == ((t & k) == 0));
            float mkx = kx[t], pkx = kx[prt];
            int   mix = ox[t], pix = ox[prt];
            float mky = ky[t], pky = ky[prt];
            int   miy = oy[t], piy = oy[prt];
            __syncthreads();
            bool lessx = (mkx < pkx) || (mkx == pkx && mix < pix);
            bool takex = (lessx == keep_small);
            kx[t] = takex ? mkx : pkx;  ox[t] = takex ? mix : pix;
            bool lessy = (mky < pky) || (mky == pky && miy < piy);
            bool takey = (lessy == keep_small);
            ky[t] = takey ? mky : pky;  oy[t] = takey ? miy : piy;
            __syncthreads();
        }
    }

    // Static extremes (groups of 4, warps of 32) over sorted coords.
    if (t < 32) {
        xgl[t] = kx[4 * t]; xgh[t] = kx[4 * t + 3];
        ygl[t] = ky[4 * t]; ygh[t] = ky[4 * t + 3];
    }
    if (t < 4) {
        wxl[t] = kx[32 * t]; wxh[t] = kx[32 * t + 31];
        wyl[t] = ky[32 * t]; wyh[t] = ky[32 * t + 31];
    }

    const float x = kx[t];
    const float y = ky[t];
    const float twoKx = TWOK * x;
    const float twoKy = TWOK * y;
    const float Kx2 = KCOEF * x * x;
    const float Ky2 = KCOEF * y * y;
    float areg = -Kx2;
    float breg = -Ky2;
    sx[t] = make_float2(x, areg);
    sy[t] = make_float2(y, breg);
    __syncthreads();

    const float4* a4y = reinterpret_cast<const float4*>(sy);
    const float4* a4x = reinterpret_cast<const float4*>(sx);

    for (int it = 0; it < NITER; ++it) {
        // ---- f-update (rows; reduce over sy) ----
        float a_new;
        if (it == 0) {
            a_new = lse_full(sy, twoKx);
        } else {
            float mx_est = -7.0f - areg;
            // group test (lane tests group g = lane): keep g iff
            // K * mindist(warp x-range, group y-range)^2 <= bpw[g] + WA + 7 + TH
            float md = fmaxf(fmaxf(ygl[lane] - wxh[myw], wxl[myw] - ygh[lane]), 0.f);
            bool fire = (KCOEF * md * md <= bpw[lane] + wxp[myw] + 7.0f + TH_SKIP);
            unsigned mask = __ballot_sync(0xffffffffu, fire);
            float s0 = 0.f, s1 = 0.f;
            unsigned m = mask;
            while (m) {                                   // warp-uniform
                int g = __ffs(m) - 1; m &= m - 1;
                float4 u = a4y[2 * g], w = a4y[2 * g + 1];
                s0 += ex2f(fmaf(twoKx, u.x, u.y) - mx_est);
                s1 += ex2f(fmaf(twoKx, u.z, u.w) - mx_est);
                s0 += ex2f(fmaf(twoKx, w.x, w.y) - mx_est);
                s1 += ex2f(fmaf(twoKx, w.z, w.w) - mx_est);
            }
            float s = s0 + s1;
            a_new = -(7.0f + mx_est + lg2f(s));
            bool bad = !(s >= SMIN && s <= SMAXB);
            if (__any_sync(0xffffffffu, bad)) a_new = lse_full(sy, twoKx);
        }
        float amov = fabsf(a_new - areg);
        areg = a_new;
        sx[t].y = a_new;
        float qa = a_new + Kx2;                           // current w of this row
        float q2 = fmaxf(qa, __shfl_xor_sync(0xffffffffu, qa, 1));
        q2 = fmaxf(q2, __shfl_xor_sync(0xffffffffu, q2, 2));
        if ((t & 3) == 0) apw[t >> 2] = q2;
        float wm = warp_max(qa);
        if (lane == 0) wxp[myw] = wm;
        __syncthreads();

        // ---- g-update (cols; reduce over sx) ----
        float b_new;
        if (it == 0) {
            b_new = lse_full(sx, twoKy);
        } else {
            float my_est = -7.0f - breg;
            float md = fmaxf(fmaxf(xgl[lane] - wyh[myw], wyl[myw] - xgh[lane]), 0.f);
            bool fire = (KCOEF * md * md <= apw[lane] + wyp[myw] + 7.0f + TH_SKIP);
            unsigned mask = __ballot_sync(0xffffffffu, fire);
            float s0 = 0.f, s1 = 0.f;
            unsigned m = mask;
            while (m) {
                int g = __ffs(m) - 1; m &= m - 1;
                float4 u = a4x[2 * g], w = a4x[2 * g + 1];
                s0 += ex2f(fmaf(twoKy, u.x, u.y) - my_est);
                s1 += ex2f(fmaf(twoKy, u.z, u.w) - my_est);
                s0 += ex2f(fmaf(twoKy, w.x, w.y) - my_est);
                s1 += ex2f(fmaf(twoKy, w.z, w.w) - my_est);
            }
            float s = s0 + s1;
            b_new = -(7.0f + my_est + lg2f(s));
            bool bad = !(s >= SMIN && s <= SMAXB);
            if (__any_sync(0xffffffffu, bad)) b_new = lse_full(sx, twoKy);
        }
        float bmov = fabsf(b_new - breg);
        breg = b_new;
        sy[t].y = b_new;
        float qb = b_new + Ky2;
        float q2b = fmaxf(qb, __shfl_xor_sync(0xffffffffu, qb, 1));
        q2b = fmaxf(q2b, __shfl_xor_sync(0xffffffffu, q2b, 2));
        if ((t & 3) == 0) bpw[t >> 2] = q2b;
        float wn = warp_max(qb);
        if (lane == 0) wyp[myw] = wn;

        int moved = (amov > CTOL) || (bmov > CTOL);
        if (!__syncthreads_or(moved)) break;
    }

    // ---- Plan accumulation: thread t = sorted row t; fixed-point atomic adds ----
    // plan_tj = 2^(E), E = a + 2Kx*y_j + b_j.
    // Group keep test: K*mindist^2 <= wxp[myw] + bpw[g] + PLAN_TH.
    {
        const int oi = ox[t];
        unsigned long long* rowp =
            g_accum + (size_t)(p & (NCOPY - 1)) * (DD * DD) + (size_t)oi * DD;
        float md = fmaxf(fmaxf(ygl[lane] - wxh[myw], wxl[myw] - ygh[lane]), 0.f);
        bool fire = (KCOEF * md * md <= bpw[lane] + wxp[myw] + PLAN_TH);
        unsigned mask = __ballot_sync(0xffffffffu, fire);
        unsigned m = mask;
        while (m) {
            int g = __ffs(m) - 1; m &= m - 1;
            float4 u = a4y[2 * g], w = a4y[2 * g + 1];
            float E0 = fmaf(twoKx, u.x, u.y) + areg;
            float E1 = fmaf(twoKx, u.z, u.w) + areg;
            float E2 = fmaf(twoKx, w.x, w.y) + areg;
            float E3 = fmaf(twoKx, w.z, w.w) + areg;
            if (E0 > E_TH)
                atomicAdd(rowp + oy[4 * g + 0], __float2ull_rn(ex2f(E0) * FIX_SCALE));
            if (E1 > E_TH)
                atomicAdd(rowp + oy[4 * g + 1], __float2ull_rn(ex2f(E1) * FIX_SCALE));
            if (E2 > E_TH)
                atomicAdd(rowp + oy[4 * g + 2], __float2ull_rn(ex2f(E2) * FIX_SCALE));
            if (E3 > E_TH)
                atomicAdd(rowp + oy[4 * g + 3], __float2ull_rn(ex2f(E3) * FIX_SCALE));
        }
    }
}

__global__ void __launch_bounds__(256) zero_accum_kernel() {
    const int idx = blockIdx.x * 256 + threadIdx.x;
    g_accum[idx] = 0ull;
}

// Sum 32 fixed-point copies (exact integer sum -> deterministic), scale, add delta.
__global__ void __launch_bounds__(256) reduce_b_kernel(const float* __restrict__ delta) {
    const int idx = blockIdx.x * 256 + threadIdx.x;
    unsigned long long tot = 0ull;
#pragma unroll
    for (int c = 0; c < NCOPY; ++c) tot += g_accum[(size_t)c * (DD * DD) + idx];
    g_ot[idx] = (float)((double)tot * ((double)OTSCALE / (double)FIX_SCALE)) + delta[idx];
}

// out[p, :] = X[p, :] @ ot  -- measured-best config (11.0us, occ 78%).
__global__ void __launch_bounds__(128) gemm_out_kernel(const float* __restrict__ X,
                                                       float* __restrict__ out) {
    __shared__ float xs[DD];
    const int p = blockIdx.x;
    const int t = threadIdx.x;
    xs[t] = X[(size_t)p * DD + t];
    __syncthreads();
    float a0 = 0.f, a1 = 0.f, a2 = 0.f, a3 = 0.f;
#pragma unroll 8
    for (int i = 0; i < DD; i += 4) {
        a0 = fmaf(xs[i + 0], g_ot[(i + 0) * DD + t], a0);
        a1 = fmaf(xs[i + 1], g_ot[(i + 1) * DD + t], a1);
        a2 = fmaf(xs[i + 2], g_ot[(i + 2) * DD + t], a2);
        a3 = fmaf(xs[i + 3], g_ot[(i + 3) * DD + t], a3);
    }
    out[(size_t)p * DD + t] = (a0 + a1) + (a2 + a3);
}

extern "C" void kernel_launch(void* const* d_in, const int* in_sizes, int n_in,
                              void* d_out, int out_size) {
    const float* X = (const float*)d_in[0];      // [8,256,128]
    const float* Y = (const float*)d_in[1];      // [8,256,128]
    const float* delta = (const float*)d_in[2];  // [128,128]
    float* out = (float*)d_out;                  // [8,256,128] float32

    zero_accum_kernel<<<(NCOPY * DD * DD) / 256, 256>>>();
    sinkhorn_kernel<<<NPROB, 128>>>(X, Y);
    reduce_b_kernel<<<(DD * DD) / 256, 256>>>(delta);
    gemm_out_kernel<<<NPROB, 128>>>(X, out);
}

// round 14
// speedup vs baseline: 1.5788x; 1.0067x over previous
#include <cuda_runtime.h>
#include <cstdint>

// Problem constants
#define NPROB 2048      // B*S = 8*256
#define DD    128       // feature dim (m = n = 128)
#define NITER 20
#define NB    128       // LUT bins

// K = (SCALE/eps) * log2(e) = 3000 * log2(e)
#define KCOEF 4328.085098989891f
#define TWOK  8656.170197979782f
#define INVK  2.3105011120474482e-4f
// ot scale: n * SCALE / NPROB = 128*300/2048
#define OTSCALE 18.75f

#define NCOPY   32
#define TH_SKIP 34.0f            // keep terms within 2^-34 of est. max
#define SMIN    2.44140625e-4f   // 2^-12: below this the window may clip real mass
#define SMAXB   1.0e30f          // overflow-only upper guard
#define PLAN_TH 30.0f            // plan keep bound (log2)
#define E_TH    -30.0f           // drop plan entries below 2^-30 (ot err <= 3.5e-5)
#define CTOL    1.0e-4f          // convergence tol (log2 units)
#define FIX_SCALE 1099511627776.0f // 2^40 fixed-point scale

__device__ unsigned long long g_accum[(size_t)NCOPY * DD * DD];
__device__ float g_ot[DD * DD];

__device__ __forceinline__ float ex2f(float x) {
    float r; asm("ex2.approx.ftz.f32 %0, %1;" : "=f"(r) : "f"(x)); return r;
}
__device__ __forceinline__ float lg2f(float x) {
    float r; asm("lg2.approx.f32 %0, %1;" : "=f"(r) : "f"(x)); return r;
}
__device__ __forceinline__ float warp_max(float v) {
#pragma unroll
    for (int o = 16; o; o >>= 1) v = fmaxf(v, __shfl_xor_sync(0xffffffffu, v, o));
    return v;
}

// Full two-pass LSE sweep (it=0 + guard fallback; warp-uniform call).
__device__ __forceinline__ float lse_full(const float2* __restrict__ arr, float twoKc) {
    const float4* a4 = reinterpret_cast<const float4*>(arr);
    float m0 = -1e30f, m1 = -1e30f, m2 = -1e30f, m3 = -1e30f;
#pragma unroll 8
    for (int q = 0; q < DD / 4; ++q) {
        float4 u = a4[2 * q];
        float4 w = a4[2 * q + 1];
        m0 = fmaxf(m0, fmaf(twoKc, u.x, u.y));
        m1 = fmaxf(m1, fmaf(twoKc, u.z, u.w));
        m2 = fmaxf(m2, fmaf(twoKc, w.x, w.y));
        m3 = fmaxf(m3, fmaf(twoKc, w.z, w.w));
    }
    float mx = fmaxf(fmaxf(m0, m1), fmaxf(m2, m3));
    float s0 = 0.f, s1 = 0.f, s2 = 0.f, s3 = 0.f;
#pragma unroll 8
    for (int q = 0; q < DD / 4; ++q) {
        float4 u = a4[2 * q];
        float4 w = a4[2 * q + 1];
        s0 += ex2f(fmaf(twoKc, u.x, u.y) - mx);
        s1 += ex2f(fmaf(twoKc, u.z, u.w) - mx);
        s2 += ex2f(fmaf(twoKc, w.x, w.y) - mx);
        s3 += ex2f(fmaf(twoKc, w.z, w.w) - mx);
    }
    float s = (s0 + s1) + (s2 + s3);
    return -(7.0f + mx + lg2f(s));
}

// Element window [lo,hi] -> index range via bin LUT (O(1), 2 LDS, no dep chain).
// LUT[q] = #keys < kmin + q/invw; widened 1 bin each side for rounding safety.
// Over-inclusion is harmless: every element is a legitimate LSE term.
__device__ __forceinline__ void lut_range(const int* __restrict__ lut,
                                          float kmin, float invw,
                                          float lo, float hi,
                                          int& jlo, int& jhi) {
    int bl = __float2int_rd((lo - kmin) * invw) - 1;
    bl = bl < 0 ? 0 : (bl > NB ? NB : bl);
    int bh = __float2int_rd((hi - kmin) * invw) + 2;
    bh = bh < 0 ? 0 : (bh > NB ? NB : bh);
    jlo = lut[bl];
    jhi = lut[bh];
}

// Per-lane one-pass windowed sum with stale shift (proven numerics).
__device__ __forceinline__ float win_sum(const float2* __restrict__ arr,
                                         float twoKc, float mx_est,
                                         int jlo, int jhi) {
    float s0 = 0.f, s1 = 0.f;
    int j = jlo;
    for (; j + 1 < jhi; j += 2) {
        float2 e0 = arr[j];
        float2 e1 = arr[j + 1];
        s0 += ex2f(fmaf(twoKc, e0.x, e0.y) - mx_est);
        s1 += ex2f(fmaf(twoKc, e1.x, e1.y) - mx_est);
    }
    if (j < jhi) {
        float2 e = arr[j];
        s0 += ex2f(fmaf(twoKc, e.x, e.y) - mx_est);
    }
    return s0 + s1;
}

__global__ void __launch_bounds__(128) sinkhorn_kernel(const float* __restrict__ X,
                                                       const float* __restrict__ Y) {
    __shared__ __align__(16) float2 sx[DD];   // {sorted x, pot a}
    __shared__ __align__(16) float2 sy[DD];   // {sorted y, pot b}
    __shared__ int ox[DD], oy[DD];            // original indices
    __shared__ __align__(16) float kx[DD], ky[DD];   // sorted coords
    __shared__ int lutx[NB + 1], luty[NB + 1];
    __shared__ float wxp[4], wyp[4];          // per-warp maxes of w = pot + K*coord^2
    __shared__ float sc[4];                   // kminx, invwx, kminy, invwy

    const int p = blockIdx.x;
    const int t = threadIdx.x;

    kx[t] = X[(size_t)p * DD + t]; ox[t] = t;
    ky[t] = Y[(size_t)p * DD + t]; oy[t] = t;
    if (t < 4) { wxp[t] = 0.f; wyp[t] = 0.f; }   // w == 0 at init
    __syncthreads();

    // Bitonic sort both (kx,ox) and (ky,oy) ascending; index tiebreak.
    for (int k = 2; k <= DD; k <<= 1) {
        for (int j = k >> 1; j > 0; j >>= 1) {
            int prt = t ^ j;
            bool keep_small = ((t < prt) == ((t & k) == 0));
            float mkx = kx[t], pkx = kx[prt];
            int   mix = ox[t], pix = ox[prt];
            float mky = ky[t], pky = ky[prt];
            int   miy = oy[t], piy = oy[prt];
            __syncthreads();
            bool lessx = (mkx < pkx) || (mkx == pkx && mix < pix);
            bool takex = (lessx == keep_small);
            kx[t] = takex ? mkx : pkx;  ox[t] = takex ? mix : pix;
            bool lessy = (mky < pky) || (mky == pky && miy < piy);
            bool takey = (lessy == keep_small);
            ky[t] = takey ? mky : pky;  oy[t] = takey ? miy : piy;
            __syncthreads();
        }
    }

    // Build bin LUTs (once).
    if (t == 0) {
        sc[0] = kx[0];  sc[1] = (float)NB / (kx[DD - 1] - kx[0]);
        sc[2] = ky[0];  sc[3] = (float)NB / (ky[DD - 1] - ky[0]);
        lutx[NB] = DD;  luty[NB] = DD;
    }
    __syncthreads();
    {
        float wx = 1.0f / sc[1], wy = 1.0f / sc[3];
        float bx = sc[0] + (float)t * wx;
        float by = sc[2] + (float)t * wy;
        int cx = 0, cy = 0;
#pragma unroll
        for (int st = 128; st; st >>= 1) {
            int c = cx + st;
            if (c <= DD && kx[c - 1] < bx) cx = c;
            int c2 = cy + st;
            if (c2 <= DD && ky[c2 - 1] < by) cy = c2;
        }
        lutx[t] = cx;
        luty[t] = cy;
    }

    const float x = kx[t];
    const float y = ky[t];
    const float twoKx = TWOK * x;
    const float twoKy = TWOK * y;
    const float Kx2 = KCOEF * x * x;
    const float Ky2 = KCOEF * y * y;
    float areg = -Kx2;
    float breg = -Ky2;
    sx[t] = make_float2(x, areg);
    sy[t] = make_float2(y, breg);
    __syncthreads();

    const float kminy = sc[2], invwy = sc[3];
    const float kminx = sc[0], invwx = sc[1];

    for (int it = 0; it < NITER; ++it) {
        // ---- f-update (rows; reduce over sy) ----
        float a_new;
        if (it == 0) {
            a_new = lse_full(sy, twoKx);
        } else {
            float wmaxy = fmaxf(fmaxf(wyp[0], wyp[1]), fmaxf(wyp[2], wyp[3]));
            float mx_est = -7.0f - areg;
            // keep j iff (x - y_j)^2 < r2 (upper bound vs stale-max threshold)
            float r2 = fmaf(x, x, (wmaxy + 7.0f + TH_SKIP + areg) * INVK);
            float s = 0.f;
            if (r2 > 0.f) {
                float r = sqrtf(r2);
                int jlo, jhi;
                lut_range(luty, kminy, invwy, x - r, x + r, jlo, jhi);
                s = win_sum(sy, twoKx, mx_est, jlo, jhi);
            }
            a_new = -(7.0f + mx_est + lg2f(s));
            bool bad = !(s >= SMIN && s <= SMAXB);
            if (__any_sync(0xffffffffu, bad)) a_new = lse_full(sy, twoKx);
        }
        float amov = fabsf(a_new - areg);
        areg = a_new;
        sx[t].y = a_new;
        float wm = warp_max(a_new + Kx2);
        if ((t & 31) == 0) wxp[t >> 5] = wm;
        __syncthreads();

        // ---- g-update (cols; reduce over sx) ----
        float b_new;
        if (it == 0) {
            b_new = lse_full(sx, twoKy);
        } else {
            float wmaxx = fmaxf(fmaxf(wxp[0], wxp[1]), fmaxf(wxp[2], wxp[3]));
            float my_est = -7.0f - breg;
            float r2 = fmaf(y, y, (wmaxx + 7.0f + TH_SKIP + breg) * INVK);
            float s = 0.f;
            if (r2 > 0.f) {
                float r = sqrtf(r2);
                int jlo, jhi;
                lut_range(lutx, kminx, invwx, y - r, y + r, jlo, jhi);
                s = win_sum(sx, twoKy, my_est, jlo, jhi);
            }
            b_new = -(7.0f + my_est + lg2f(s));
            bool bad = !(s >= SMIN && s <= SMAXB);
            if (__any_sync(0xffffffffu, bad)) b_new = lse_full(sx, twoKy);
        }
        float bmov = fabsf(b_new - breg);
        breg = b_new;
        sy[t].y = b_new;
        float wn = warp_max(b_new + Ky2);
        if ((t & 31) == 0) wyp[t >> 5] = wn;

        int moved = (amov > CTOL) || (bmov > CTOL);
        if (!__syncthreads_or(moved)) break;
    }

    // ---- Plan accumulation: thread t = sorted row t; per-lane LUT window ----
    // E = a + 2Kx*y_j + b_j = (a + Kx^2) + w_j - K(x-y_j)^2; keep iff E >= -PLAN_TH.
    {
        const int oi = ox[t];
        unsigned long long* rowp =
            g_accum + (size_t)(p & (NCOPY - 1)) * (DD * DD) + (size_t)oi * DD;
        float wmaxy = fmaxf(fmaxf(wyp[0], wyp[1]), fmaxf(wyp[2], wyp[3]));
        float r2 = fmaf(x, x, (wmaxy + areg + PLAN_TH) * INVK);
        if (r2 > 0.f) {
            float r = sqrtf(r2);
            int jlo, jhi;
            lut_range(luty, kminy, invwy, x - r, x + r, jlo, jhi);
            for (int j = jlo; j < jhi; ++j) {
                float2 e = sy[j];
                float E = fmaf(twoKx, e.x, e.y) + areg;
                if (E > E_TH)
                    atomicAdd(rowp + oy[j], __float2ull_rn(ex2f(E) * FIX_SCALE));
            }
        }
    }
}

__global__ void __launch_bounds__(256) zero_accum_kernel() {
    const int idx = blockIdx.x * 256 + threadIdx.x;
    g_accum[idx] = 0ull;
}

// Sum 32 fixed-point copies (exact integer sum -> deterministic), scale, add delta.
__global__ void __launch_bounds__(256) reduce_b_kernel(const float* __restrict__ delta) {
    const int idx = blockIdx.x * 256 + threadIdx.x;
    unsigned long long tot = 0ull;
#pragma unroll
    for (int c = 0; c < NCOPY; ++c) tot += g_accum[(size_t)c * (DD * DD) + idx];
    g_ot[idx] = (float)((double)tot * ((double)OTSCALE / (double)FIX_SCALE)) + delta[idx];
}

// out[p, :] = X[p, :] @ ot  -- measured-best config (11.0us, occ 78%).
__global__ void __launch_bounds__(128) gemm_out_kernel(const float* __restrict__ X,
                                                       float* __restrict__ out) {
    __shared__ float xs[DD];
    const int p = blockIdx.x;
    const int t = threadIdx.x;
    xs[t] = X[(size_t)p * DD + t];
    __syncthreads();
    float a0 = 0.f, a1 = 0.f, a2 = 0.f, a3 = 0.f;
#pragma unroll 8
    for (int i = 0; i < DD; i += 4) {
        a0 = fmaf(xs[i + 0], g_ot[(i + 0) * DD + t], a0);
        a1 = fmaf(xs[i + 1], g_ot[(i + 1) * DD + t], a1);
        a2 = fmaf(xs[i + 2], g_ot[(i + 2) * DD + t], a2);
        a3 = fmaf(xs[i + 3], g_ot[(i + 3) * DD + t], a3);
    }
    out[(size_t)p * DD + t] = (a0 + a1) + (a2 + a3);
}

extern "C" void kernel_launch(void* const* d_in, const int* in_sizes, int n_in,
                              void* d_out, int out_size) {
    const float* X = (const float*)d_in[0];      // [8,256,128]
    const float* Y = (const float*)d_in[1];      // [8,256,128]
    const float* delta = (const float*)d_in[2];  // [128,128]
    float* out = (float*)d_out;                  // [8,256,128] float32

    zero_accum_kernel<<<(NCOPY * DD * DD) / 256, 256>>>();
    sinkhorn_kernel<<<NPROB, 128>>>(X, Y);
    reduce_b_kernel<<<(DD * DD) / 256, 256>>>(delta);
    gemm_out_kernel<<<NPROB, 128>>>(X, out);
}

// round 15
// speedup vs baseline: 1.6163x; 1.0238x over previous
#include <cuda_runtime.h>
#include <cstdint>

// Problem constants
#define NPROB 2048      // B*S = 8*256
#define DD    128       // feature dim (m = n = 128)
#define NITER 20
#define NB    128       // LUT bins

// K = (SCALE/eps) * log2(e) = 3000 * log2(e)
#define KCOEF 4328.085098989891f
#define TWOK  8656.170197979782f
#define INVK  2.3105011120474482e-4f
// ot scale: n * SCALE / NPROB = 128*300/2048
#define OTSCALE 18.75f

#define NCOPY   32
#define TH_SKIP 46.0f            // widened: tolerate 24-unit downward moves
#define SMIN    5.9604644775e-8f // 2^-24 (drop bound 2^7 * 2^(24-46) = 2^-15, unchanged)
#define SMAXB   1.0e30f          // overflow-only upper guard
#define PLAN_TH 30.0f            // plan keep bound (log2)
#define E_TH    -30.0f           // drop plan entries below 2^-30 (ot err <= 3.5e-5)
#define CTOL    1.0e-4f          // convergence tol (log2 units)
#define FIX_SCALE 1099511627776.0f // 2^40 fixed-point scale

__device__ unsigned long long g_accum[(size_t)NCOPY * DD * DD];
__device__ float g_ot[DD * DD];

__device__ __forceinline__ float ex2f(float x) {
    float r; asm("ex2.approx.ftz.f32 %0, %1;" : "=f"(r) : "f"(x)); return r;
}
__device__ __forceinline__ float lg2f(float x) {
    float r; asm("lg2.approx.f32 %0, %1;" : "=f"(r) : "f"(x)); return r;
}
__device__ __forceinline__ float warp_max(float v) {
#pragma unroll
    for (int o = 16; o; o >>= 1) v = fmaxf(v, __shfl_xor_sync(0xffffffffu, v, o));
    return v;
}

// Full two-pass LSE sweep (it=0 + rare guard fallback; warp-uniform call).
__device__ __forceinline__ float lse_full(const float2* __restrict__ arr, float twoKc) {
    const float4* a4 = reinterpret_cast<const float4*>(arr);
    float m0 = -1e30f, m1 = -1e30f, m2 = -1e30f, m3 = -1e30f;
#pragma unroll 8
    for (int q = 0; q < DD / 4; ++q) {
        float4 u = a4[2 * q];
        float4 w = a4[2 * q + 1];
        m0 = fmaxf(m0, fmaf(twoKc, u.x, u.y));
        m1 = fmaxf(m1, fmaf(twoKc, u.z, u.w));
        m2 = fmaxf(m2, fmaf(twoKc, w.x, w.y));
        m3 = fmaxf(m3, fmaf(twoKc, w.z, w.w));
    }
    float mx = fmaxf(fmaxf(m0, m1), fmaxf(m2, m3));
    float s0 = 0.f, s1 = 0.f, s2 = 0.f, s3 = 0.f;
#pragma unroll 8
    for (int q = 0; q < DD / 4; ++q) {
        float4 u = a4[2 * q];
        float4 w = a4[2 * q + 1];
        s0 += ex2f(fmaf(twoKc, u.x, u.y) - mx);
        s1 += ex2f(fmaf(twoKc, u.z, u.w) - mx);
        s2 += ex2f(fmaf(twoKc, w.x, w.y) - mx);
        s3 += ex2f(fmaf(twoKc, w.z, w.w) - mx);
    }
    float s = (s0 + s1) + (s2 + s3);
    return -(7.0f + mx + lg2f(s));
}

// Element window [lo,hi] -> index range via bin LUT (O(1), 2 LDS, no dep chain).
__device__ __forceinline__ void lut_range(const int* __restrict__ lut,
                                          float kmin, float invw,
                                          float lo, float hi,
                                          int& jlo, int& jhi) {
    int bl = __float2int_rd((lo - kmin) * invw) - 1;
    bl = bl < 0 ? 0 : (bl > NB ? NB : bl);
    int bh = __float2int_rd((hi - kmin) * invw) + 2;
    bh = bh < 0 ? 0 : (bh > NB ? NB : bh);
    jlo = lut[bl];
    jhi = lut[bh];
}

// Per-lane one-pass windowed sum with stale shift (proven numerics).
__device__ __forceinline__ float win_sum(const float2* __restrict__ arr,
                                         float twoKc, float mx_est,
                                         int jlo, int jhi) {
    float s0 = 0.f, s1 = 0.f;
    int j = jlo;
    for (; j + 1 < jhi; j += 2) {
        float2 e0 = arr[j];
        float2 e1 = arr[j + 1];
        s0 += ex2f(fmaf(twoKc, e0.x, e0.y) - mx_est);
        s1 += ex2f(fmaf(twoKc, e1.x, e1.y) - mx_est);
    }
    if (j < jhi) {
        float2 e = arr[j];
        s0 += ex2f(fmaf(twoKc, e.x, e.y) - mx_est);
    }
    return s0 + s1;
}

__global__ void __launch_bounds__(128, 12) sinkhorn_kernel(const float* __restrict__ X,
                                                           const float* __restrict__ Y) {
    __shared__ __align__(16) float2 sx[DD];   // {sorted x, pot a}
    __shared__ __align__(16) float2 sy[DD];   // {sorted y, pot b}
    __shared__ int ox[DD], oy[DD];            // original indices
    __shared__ __align__(16) float kx[DD], ky[DD];   // sorted coords
    __shared__ int lutx[NB + 1], luty[NB + 1];
    __shared__ float wxp[4], wyp[4];          // per-warp maxes of w = pot + K*coord^2
    __shared__ float sc[4];                   // kminx, invwx, kminy, invwy

    const int p = blockIdx.x;
    const int t = threadIdx.x;

    kx[t] = X[(size_t)p * DD + t]; ox[t] = t;
    ky[t] = Y[(size_t)p * DD + t]; oy[t] = t;
    if (t < 4) { wxp[t] = 0.f; wyp[t] = 0.f; }   // w == 0 at init
    __syncthreads();

    // Bitonic sort both (kx,ox) and (ky,oy) ascending; index tiebreak.
    for (int k = 2; k <= DD; k <<= 1) {
        for (int j = k >> 1; j > 0; j >>= 1) {
            int prt = t ^ j;
            bool keep_small = ((t < prt) == ((t & k) == 0));
            float mkx = kx[t], pkx = kx[prt];
            int   mix = ox[t], pix = ox[prt];
            float mky = ky[t], pky = ky[prt];
            int   miy = oy[t], piy = oy[prt];
            __syncthreads();
            bool lessx = (mkx < pkx) || (mkx == pkx && mix < pix);
            bool takex = (lessx == keep_small);
            kx[t] = takex ? mkx : pkx;  ox[t] = takex ? mix : pix;
            bool lessy = (mky < pky) || (mky == pky && miy < piy);
            bool takey = (lessy == keep_small);
            ky[t] = takey ? mky : pky;  oy[t] = takey ? miy : piy;
            __syncthreads();
        }
    }

    // Build bin LUTs (once).
    if (t == 0) {
        sc[0] = kx[0];  sc[1] = (float)NB / (kx[DD - 1] - kx[0]);
        sc[2] = ky[0];  sc[3] = (float)NB / (ky[DD - 1] - ky[0]);
        lutx[NB] = DD;  luty[NB] = DD;
    }
    __syncthreads();
    {
        float wx = 1.0f / sc[1], wy = 1.0f / sc[3];
        float bx = sc[0] + (float)t * wx;
        float by = sc[2] + (float)t * wy;
        int cx = 0, cy = 0;
#pragma unroll
        for (int st = 128; st; st >>= 1) {
            int c = cx + st;
            if (c <= DD && kx[c - 1] < bx) cx = c;
            int c2 = cy + st;
            if (c2 <= DD && ky[c2 - 1] < by) cy = c2;
        }
        lutx[t] = cx;
        luty[t] = cy;
    }

    const float x = kx[t];
    const float y = ky[t];
    const float twoKx = TWOK * x;
    const float twoKy = TWOK * y;
    const float Kx2 = KCOEF * x * x;
    const float Ky2 = KCOEF * y * y;
    float areg = -Kx2;
    float breg = -Ky2;
    sx[t] = make_float2(x, areg);
    sy[t] = make_float2(y, breg);
    __syncthreads();

    const float kminy = sc[2], invwy = sc[3];
    const float kminx = sc[0], invwx = sc[1];

    for (int it = 0; it < NITER; ++it) {
        // ---- f-update (rows; reduce over sy) ----
        float a_new;
        if (it == 0) {
            a_new = lse_full(sy, twoKx);
        } else {
            float wmaxy = fmaxf(fmaxf(wyp[0], wyp[1]), fmaxf(wyp[2], wyp[3]));
            float mx_est = -7.0f - areg;
            // keep j iff (x - y_j)^2 < r2 (upper bound vs stale-max threshold)
            float r2 = fmaf(x, x, (wmaxy + 7.0f + TH_SKIP + areg) * INVK);
            float s = 0.f;
            if (r2 > 0.f) {
                float r = sqrtf(r2);
                int jlo, jhi;
                lut_range(luty, kminy, invwy, x - r, x + r, jlo, jhi);
                s = win_sum(sy, twoKx, mx_est, jlo, jhi);
            }
            a_new = -(7.0f + mx_est + lg2f(s));
            bool bad = !(s >= SMIN && s <= SMAXB);
            if (__any_sync(0xffffffffu, bad)) a_new = lse_full(sy, twoKx);
        }
        float amov = fabsf(a_new - areg);
        areg = a_new;
        sx[t].y = a_new;
        float wm = warp_max(a_new + Kx2);
        if ((t & 31) == 0) wxp[t >> 5] = wm;
        __syncthreads();

        // ---- g-update (cols; reduce over sx) ----
        float b_new;
        if (it == 0) {
            b_new = lse_full(sx, twoKy);
        } else {
            float wmaxx = fmaxf(fmaxf(wxp[0], wxp[1]), fmaxf(wxp[2], wxp[3]));
            float my_est = -7.0f - breg;
            float r2 = fmaf(y, y, (wmaxx + 7.0f + TH_SKIP + breg) * INVK);
            float s = 0.f;
            if (r2 > 0.f) {
                float r = sqrtf(r2);
                int jlo, jhi;
                lut_range(lutx, kminx, invwx, y - r, y + r, jlo, jhi);
                s = win_sum(sx, twoKy, my_est, jlo, jhi);
            }
            b_new = -(7.0f + my_est + lg2f(s));
            bool bad = !(s >= SMIN && s <= SMAXB);
            if (__any_sync(0xffffffffu, bad)) b_new = lse_full(sx, twoKy);
        }
        float bmov = fabsf(b_new - breg);
        breg = b_new;
        sy[t].y = b_new;
        float wn = warp_max(b_new + Ky2);
        if ((t & 31) == 0) wyp[t >> 5] = wn;

        int moved = (amov > CTOL) || (bmov > CTOL);
        if (!__syncthreads_or(moved)) break;
    }

    // ---- Plan accumulation: thread t = sorted row t; per-lane LUT window ----
    // E = a + 2Kx*y_j + b_j; keep iff E >= -PLAN_TH (bound via (x-y)^2).
    {
        const int oi = ox[t];
        unsigned long long* rowp =
            g_accum + (size_t)(p & (NCOPY - 1)) * (DD * DD) + (size_t)oi * DD;
        float wmaxy = fmaxf(fmaxf(wyp[0], wyp[1]), fmaxf(wyp[2], wyp[3]));
        float r2 = fmaf(x, x, (wmaxy + areg + PLAN_TH) * INVK);
        if (r2 > 0.f) {
            float r = sqrtf(r2);
            int jlo, jhi;
            lut_range(luty, kminy, invwy, x - r, x + r, jlo, jhi);
            for (int j = jlo; j < jhi; ++j) {
                float2 e = sy[j];
                float E = fmaf(twoKx, e.x, e.y) + areg;
                if (E > E_TH)
                    atomicAdd(rowp + oy[j], __float2ull_rn(ex2f(E) * FIX_SCALE));
            }
        }
    }
}

__global__ void __launch_bounds__(256) zero_accum_kernel() {
    const int idx = blockIdx.x * 256 + threadIdx.x;
    g_accum[idx] = 0ull;
}

// Sum 32 fixed-point copies (exact integer sum -> deterministic), scale, add delta.
__global__ void __launch_bounds__(256) reduce_b_kernel(const float* __restrict__ delta) {
    const int idx = blockIdx.x * 256 + threadIdx.x;
    unsigned long long tot = 0ull;
#pragma unroll
    for (int c = 0; c < NCOPY; ++c) tot += g_accum[(size_t)c * (DD * DD) + idx];
    g_ot[idx] = (float)((double)tot * ((double)OTSCALE / (double)FIX_SCALE)) + delta[idx];
}

// out[p, :] = X[p, :] @ ot  -- measured-best config (11.0us, occ 78%).
__global__ void __launch_bounds__(128) gemm_out_kernel(const float* __restrict__ X,
                                                       float* __restrict__ out) {
    __shared__ float xs[DD];
    const int p = blockIdx.x;
    const int t = threadIdx.x;
    xs[t] = X[(size_t)p * DD + t];
    __syncthreads();
    float a0 = 0.f, a1 = 0.f, a2 = 0.f, a3 = 0.f;
#pragma unroll 8
    for (int i = 0; i < DD; i += 4) {
        a0 = fmaf(xs[i + 0], g_ot[(i + 0) * DD + t], a0);
        a1 = fmaf(xs[i + 1], g_ot[(i + 1) * DD + t], a1);
        a2 = fmaf(xs[i + 2], g_ot[(i + 2) * DD + t], a2);
        a3 = fmaf(xs[i + 3], g_ot[(i + 3) * DD + t], a3);
    }
    out[(size_t)p * DD + t] = (a0 + a1) + (a2 + a3);
}

extern "C" void kernel_launch(void* const* d_in, const int* in_sizes, int n_in,
                              void* d_out, int out_size) {
    const float* X = (const float*)d_in[0];      // [8,256,128]
    const float* Y = (const float*)d_in[1];      // [8,256,128]
    const float* delta = (const float*)d_in[2];  // [128,128]
    float* out = (float*)d_out;                  // [8,256,128] float32

    zero_accum_kernel<<<(NCOPY * DD * DD) / 256, 256>>>();
    sinkhorn_kernel<<<NPROB, 128>>>(X, Y);
    reduce_b_kernel<<<(DD * DD) / 256, 256>>>(delta);
    gemm_out_kernel<<<NPROB, 128>>>(X, out);
}

// round 16
// speedup vs baseline: 1.7113x; 1.0588x over previous
#include <cuda_runtime.h>
#include <cstdint>

// Problem constants
#define NPROB 2048      // B*S = 8*256
#define DD    128       // feature dim (m = n = 128)
#define NITER 20

// K = (SCALE/eps) * log2(e) = 3000 * log2(e)
#define KCOEF 4328.085098989891f
#define TWOK  8656.170197979782f
// ot scale: n * SCALE / NPROB = 128*300/2048
#define OTSCALE 18.75f

#define NCOPY   32
#define TH_SKIP 34.0f            // group-skip threshold below est. max (log2)
#define SMIN    2.44140625e-4f   // 2^-12 guard
#define SMAX    4096.0f          // 2^12 guard
#define PLAN_TH -35.0f           // plan entries below 2^-35 dropped
#define FIX_SCALE 1099511627776.0f // 2^40 fixed-point scale

__device__ unsigned long long g_accum[(size_t)NCOPY * DD * DD];
__device__ float g_ot[DD * DD];

__device__ __forceinline__ float ex2f(float x) {
    float r; asm("ex2.approx.ftz.f32 %0, %1;" : "=f"(r) : "f"(x)); return r;
}
__device__ __forceinline__ float lg2f(float x) {
    float r; asm("lg2.approx.f32 %0, %1;" : "=f"(r) : "f"(x)); return r;
}

// Full two-pass LSE sweep over 128 float2{coord,pot} entries (exact fallback).
// Returns new potential: -(7 + max_j v + log2(sum_j 2^(v-max))), v_j = twoKc*coord_j + pot_j
__device__ __forceinline__ float lse_full(const float2* __restrict__ arr, float twoKc) {
    const float4* a4 = reinterpret_cast<const float4*>(arr);
    float m0 = -1e30f, m1 = -1e30f, m2 = -1e30f, m3 = -1e30f;
#pragma unroll 8
    for (int q = 0; q < DD / 4; ++q) {
        float4 u = a4[2 * q];
        float4 w = a4[2 * q + 1];
        m0 = fmaxf(m0, fmaf(twoKc, u.x, u.y));
        m1 = fmaxf(m1, fmaf(twoKc, u.z, u.w));
        m2 = fmaxf(m2, fmaf(twoKc, w.x, w.y));
        m3 = fmaxf(m3, fmaf(twoKc, w.z, w.w));
    }
    float mx = fmaxf(fmaxf(m0, m1), fmaxf(m2, m3));
    float s0 = 0.f, s1 = 0.f, s2 = 0.f, s3 = 0.f;
#pragma unroll 8
    for (int q = 0; q < DD / 4; ++q) {
        float4 u = a4[2 * q];
        float4 w = a4[2 * q + 1];
        s0 += ex2f(fmaf(twoKc, u.x, u.y) - mx);
        s1 += ex2f(fmaf(twoKc, u.z, u.w) - mx);
        s2 += ex2f(fmaf(twoKc, w.x, w.y) - mx);
        s3 += ex2f(fmaf(twoKc, w.z, w.w) - mx);
    }
    float s = (s0 + s1) + (s2 + s3);
    return -(7.0f + mx + lg2f(s));
}

// Guarded sparse sum: sum of 2^(v - mx_est) over groups whose upper bound
// (twoKc * ext_coord + group pot max) exceeds mx_est - TH_SKIP for ANY lane.
// pmax[32]: group max of pots; eptr[32]: group extreme coord (hi if twoKc>=0).
__device__ __forceinline__ float guarded_sum(const float2* __restrict__ arr,
                                             const float* __restrict__ pmax,
                                             const float* __restrict__ eptr,
                                             float twoKc, float mx_est) {
    const float thr = mx_est - TH_SKIP;
    const float4* a4 = reinterpret_cast<const float4*>(arr);
    const float4* pm4 = reinterpret_cast<const float4*>(pmax);
    const float4* ex4 = reinterpret_cast<const float4*>(eptr);
    float sA = 0.f, sB = 0.f;
#pragma unroll
    for (int q = 0; q < 8; ++q) {
        float4 pm = pm4[q];
        float4 ex = ex4[q];
        int g = 4 * q;
        if (__any_sync(0xffffffffu, fmaf(twoKc, ex.x, pm.x) > thr)) {
            float4 u = a4[2 * g], w = a4[2 * g + 1];
            sA += ex2f(fmaf(twoKc, u.x, u.y) - mx_est);
            sB += ex2f(fmaf(twoKc, u.z, u.w) - mx_est);
            sA += ex2f(fmaf(twoKc, w.x, w.y) - mx_est);
            sB += ex2f(fmaf(twoKc, w.z, w.w) - mx_est);
        }
        if (__any_sync(0xffffffffu, fmaf(twoKc, ex.y, pm.y) > thr)) {
            float4 u = a4[2 * g + 2], w = a4[2 * g + 3];
            sA += ex2f(fmaf(twoKc, u.x, u.y) - mx_est);
            sB += ex2f(fmaf(twoKc, u.z, u.w) - mx_est);
            sA += ex2f(fmaf(twoKc, w.x, w.y) - mx_est);
            sB += ex2f(fmaf(twoKc, w.z, w.w) - mx_est);
        }
        if (__any_sync(0xffffffffu, fmaf(twoKc, ex.z, pm.z) > thr)) {
            float4 u = a4[2 * g + 4], w = a4[2 * g + 5];
            sA += ex2f(fmaf(twoKc, u.x, u.y) - mx_est);
            sB += ex2f(fmaf(twoKc, u.z, u.w) - mx_est);
            sA += ex2f(fmaf(twoKc, w.x, w.y) - mx_est);
            sB += ex2f(fmaf(twoKc, w.z, w.w) - mx_est);
        }
        if (__any_sync(0xffffffffu, fmaf(twoKc, ex.w, pm.w) > thr)) {
            float4 u = a4[2 * g + 6], w = a4[2 * g + 7];
            sA += ex2f(fmaf(twoKc, u.x, u.y) - mx_est);
            sB += ex2f(fmaf(twoKc, u.z, u.w) - mx_est);
            sA += ex2f(fmaf(twoKc, w.x, w.y) - mx_est);
            sB += ex2f(fmaf(twoKc, w.z, w.w) - mx_est);
        }
    }
    return sA + sB;
}

__global__ void __launch_bounds__(128) sinkhorn_kernel(const float* __restrict__ X,
                                                       const float* __restrict__ Y) {
    __shared__ __align__(16) float2 sx[DD];   // {sorted x, pot a}
    __shared__ __align__(16) float2 sy[DD];   // {sorted y, pot b}
    __shared__ int ox[DD], oy[DD];            // original indices
    __shared__ __align__(16) float kx[DD], ky[DD];          // sort keys
    __shared__ __align__(16) float apx[32], bpx[32];        // group pot maxes
    __shared__ __align__(16) float xlo[32], xhi[32], ylo[32], yhi[32];

    const int p = blockIdx.x;
    const int t = threadIdx.x;

    kx[t] = X[(size_t)p * DD + t]; ox[t] = t;
    ky[t] = Y[(size_t)p * DD + t]; oy[t] = t;
    __syncthreads();

    // Bitonic sort both (kx,ox) and (ky,oy) ascending; index tiebreak for total order.
    for (int k = 2; k <= DD; k <<= 1) {
        for (int j = k >> 1; j > 0; j >>= 1) {
            int prt = t ^ j;
            bool keep_small = ((t < prt) == ((t & k) == 0));
            float mkx = kx[t], pkx = kx[prt];
            int   mix = ox[t], pix = ox[prt];
            float mky = ky[t], pky = ky[prt];
            int   miy = oy[t], piy = oy[prt];
            __syncthreads();
            bool lessx = (mkx < pkx) || (mkx == pkx && mix < pix);
            bool takex = (lessx == keep_small);
            kx[t] = takex ? mkx : pkx;  ox[t] = takex ? mix : pix;
            bool lessy = (mky < pky) || (mky == pky && miy < piy);
            bool takey = (lessy == keep_small);
            ky[t] = takey ? mky : pky;  oy[t] = takey ? miy : piy;
            __syncthreads();
        }
    }

    const float x = kx[t];
    const float y = ky[t];
    const float twoKx = TWOK * x;
    const float twoKy = TWOK * y;
    float areg = -KCOEF * x * x;
    float breg = -KCOEF * y * y;
    sx[t] = make_float2(x, areg);
    sy[t] = make_float2(y, breg);
    if (t < 32) {
        xlo[t] = kx[4 * t]; xhi[t] = kx[4 * t + 3];
        ylo[t] = ky[4 * t]; yhi[t] = ky[4 * t + 3];
    }
    __syncthreads();

    const float* eyp = (twoKx >= 0.f) ? yhi : ylo;  // extreme y per group for f bound
    const float* exq = (twoKy >= 0.f) ? xhi : xlo;  // extreme x per group for g bound

    for (int it = 0; it < NITER; ++it) {
        // ---- f-update (rows; reduce over sy) ----
        float a_new = 0.f;
        bool full = (it == 0);
        if (!full) {
            float mx_est = -7.0f - areg;
            float s = guarded_sum(sy, bpx, eyp, twoKx, mx_est);
            bool bad = !(s >= SMIN && s <= SMAX);
            a_new = -(7.0f + mx_est + lg2f(s));
            full = __any_sync(0xffffffffu, bad);
        }
        if (full) a_new = lse_full(sy, twoKx);
        areg = a_new;
        float qa = a_new;
        qa = fmaxf(qa, __shfl_xor_sync(0xffffffffu, qa, 1));
        qa = fmaxf(qa, __shfl_xor_sync(0xffffffffu, qa, 2));
        sx[t].y = a_new;
        if ((t & 3) == 0) apx[t >> 2] = qa;
        __syncthreads();

        // ---- g-update (cols; reduce over sx) ----
        float b_new = 0.f;
        full = (it == 0);
        if (!full) {
            float mx_est = -7.0f - breg;
            float s = guarded_sum(sx, apx, exq, twoKy, mx_est);
            bool bad = !(s >= SMIN && s <= SMAX);
            b_new = -(7.0f + mx_est + lg2f(s));
            full = __any_sync(0xffffffffu, bad);
        }
        if (full) b_new = lse_full(sx, twoKy);
        breg = b_new;
        float qb = b_new;
        qb = fmaxf(qb, __shfl_xor_sync(0xffffffffu, qb, 1));
        qb = fmaxf(qb, __shfl_xor_sync(0xffffffffu, qb, 2));
        sy[t].y = b_new;
        if ((t & 3) == 0) bpx[t >> 2] = qb;
        __syncthreads();
    }

    // ---- Plan accumulation: thread t = sorted row t; fixed-point atomic adds ----
    // plan_ij = 2^(a_i + b_j + twoK * x_i * y_j); skip groups bounded below 2^PLAN_TH.
    {
        const int oi = ox[t];
        unsigned long long* rowp =
            g_accum + (size_t)(p & (NCOPY - 1)) * (DD * DD) + (size_t)oi * DD;
        const float thr = PLAN_TH - areg;   // fire iff v_j > thr
        const float4* a4 = reinterpret_cast<const float4*>(sy);
        const float4* pm4 = reinterpret_cast<const float4*>(bpx);
        const float4* ex4 = reinterpret_cast<const float4*>(eyp);
#pragma unroll
        for (int q = 0; q < 8; ++q) {
            float4 pm = pm4[q];
            float4 ex = ex4[q];
#pragma unroll
            for (int h = 0; h < 4; ++h) {
                float bnd = (h == 0) ? fmaf(twoKx, ex.x, pm.x)
                          : (h == 1) ? fmaf(twoKx, ex.y, pm.y)
                          : (h == 2) ? fmaf(twoKx, ex.z, pm.z)
                                     : fmaf(twoKx, ex.w, pm.w);
                if (__any_sync(0xffffffffu, bnd > thr)) {
                    int g = 4 * q + h;
                    float4 u = a4[2 * g], w = a4[2 * g + 1];
                    float E0 = fmaf(twoKx, u.x, u.y) + areg;
                    float E1 = fmaf(twoKx, u.z, u.w) + areg;
                    float E2 = fmaf(twoKx, w.x, w.y) + areg;
                    float E3 = fmaf(twoKx, w.z, w.w) + areg;
                    if (E0 > -40.f)
                        atomicAdd(rowp + oy[4 * g + 0],
                                  (unsigned long long)(ex2f(E0) * FIX_SCALE));
                    if (E1 > -40.f)
                        atomicAdd(rowp + oy[4 * g + 1],
                                  (unsigned long long)(ex2f(E1) * FIX_SCALE));
                    if (E2 > -40.f)
                        atomicAdd(rowp + oy[4 * g + 2],
                                  (unsigned long long)(ex2f(E2) * FIX_SCALE));
                    if (E3 > -40.f)
                        atomicAdd(rowp + oy[4 * g + 3],
                                  (unsigned long long)(ex2f(E3) * FIX_SCALE));
                }
            }
        }
    }
}

__global__ void __launch_bounds__(256) zero_accum_kernel() {
    const int idx = blockIdx.x * 256 + threadIdx.x;
    g_accum[idx] = 0ull;
}

// Sum 32 fixed-point copies (exact integer sum -> deterministic), scale, add delta.
__global__ void __launch_bounds__(256) reduce_b_kernel(const float* __restrict__ delta) {
    const int idx = blockIdx.x * 256 + threadIdx.x;
    unsigned long long tot = 0ull;
#pragma unroll
    for (int c = 0; c < NCOPY; ++c) tot += g_accum[(size_t)c * (DD * DD) + idx];
    g_ot[idx] = (float)((double)tot * ((double)OTSCALE / (double)FIX_SCALE)) + delta[idx];
}

// out[p, :] = X[p, :] @ ot  (ot is 64KB, L2 resident)
__global__ void __launch_bounds__(128) gemm_out_kernel(const float* __restrict__ X,
                                                       float* __restrict__ out) {
    __shared__ float xs[DD];
    const int p = blockIdx.x;
    const int t = threadIdx.x;
    xs[t] = X[(size_t)p * DD + t];
    __syncthreads();
    float a0 = 0.f, a1 = 0.f, a2 = 0.f, a3 = 0.f;
#pragma unroll 8
    for (int i = 0; i < DD; i += 4) {
        a0 = fmaf(xs[i + 0], g_ot[(i + 0) * DD + t], a0);
        a1 = fmaf(xs[i + 1], g_ot[(i + 1) * DD + t], a1);
        a2 = fmaf(xs[i + 2], g_ot[(i + 2) * DD + t], a2);
        a3 = fmaf(xs[i + 3], g_ot[(i + 3) * DD + t], a3);
    }
    out[(size_t)p * DD + t] = (a0 + a1) + (a2 + a3);
}

extern "C" void kernel_launch(void* const* d_in, const int* in_sizes, int n_in,
                              void* d_out, int out_size) {
    const float* X = (const float*)d_in[0];      // [8,256,128]
    const float* Y = (const float*)d_in[1];      // [8,256,128]
    const float* delta = (const float*)d_in[2];  // [128,128]
    float* out = (float*)d_out;                  // [8,256,128] float32

    zero_accum_kernel<<<(NCOPY * DD * DD) / 256, 256>>>();
    sinkhorn_kernel<<<NPROB, 128>>>(X, Y);
    reduce_b_kernel<<<(DD * DD) / 256, 256>>>(delta);
    gemm_out_kernel<<<NPROB, 128>>>(X, out);
}

// round 17
// speedup vs baseline: 1.7301x; 1.0110x over previous
#include <cuda_runtime.h>
#include <cstdint>

// Problem constants
#define NPROB 2048      // B*S = 8*256
#define DD    128       // feature dim (m = n = 128)
#define NITER 20

// K = (SCALE/eps) * log2(e) = 3000 * log2(e)
#define KCOEF 4328.085098989891f
#define TWOK  8656.170197979782f
// ot scale: n * SCALE / NPROB = 128*300/2048
#define OTSCALE 18.75f

#define NCOPY   32
#define TH_SKIP 34.0f            // group-skip threshold below est. max (log2)
#define SMIN    2.44140625e-4f   // 2^-12 guard
#define SMAX    4096.0f          // 2^12 guard
#define PLAN_TH -30.0f           // plan group bound (validated R13-R15)
#define E_TH    -30.0f           // drop plan entries below 2^-30 (ot err <= 3.5e-5)
#define FIX_SCALE 1099511627776.0f // 2^40 fixed-point scale

__device__ unsigned long long g_accum[(size_t)NCOPY * DD * DD];
__device__ float g_ot[DD * DD];

__device__ __forceinline__ float ex2f(float x) {
    float r; asm("ex2.approx.ftz.f32 %0, %1;" : "=f"(r) : "f"(x)); return r;
}
__device__ __forceinline__ float lg2f(float x) {
    float r; asm("lg2.approx.f32 %0, %1;" : "=f"(r) : "f"(x)); return r;
}

// Full two-pass LSE sweep over 128 float2{coord,pot} entries (exact fallback).
// Returns new potential: -(7 + max_j v + log2(sum_j 2^(v-max))), v_j = twoKc*coord_j + pot_j
__device__ __forceinline__ float lse_full(const float2* __restrict__ arr, float twoKc) {
    const float4* a4 = reinterpret_cast<const float4*>(arr);
    float m0 = -1e30f, m1 = -1e30f, m2 = -1e30f, m3 = -1e30f;
#pragma unroll 8
    for (int q = 0; q < DD / 4; ++q) {
        float4 u = a4[2 * q];
        float4 w = a4[2 * q + 1];
        m0 = fmaxf(m0, fmaf(twoKc, u.x, u.y));
        m1 = fmaxf(m1, fmaf(twoKc, u.z, u.w));
        m2 = fmaxf(m2, fmaf(twoKc, w.x, w.y));
        m3 = fmaxf(m3, fmaf(twoKc, w.z, w.w));
    }
    float mx = fmaxf(fmaxf(m0, m1), fmaxf(m2, m3));
    float s0 = 0.f, s1 = 0.f, s2 = 0.f, s3 = 0.f;
#pragma unroll 8
    for (int q = 0; q < DD / 4; ++q) {
        float4 u = a4[2 * q];
        float4 w = a4[2 * q + 1];
        s0 += ex2f(fmaf(twoKc, u.x, u.y) - mx);
        s1 += ex2f(fmaf(twoKc, u.z, u.w) - mx);
        s2 += ex2f(fmaf(twoKc, w.x, w.y) - mx);
        s3 += ex2f(fmaf(twoKc, w.z, w.w) - mx);
    }
    float s = (s0 + s1) + (s2 + s3);
    return -(7.0f + mx + lg2f(s));
}

// Guarded sparse sum: sum of 2^(v - mx_est) over groups whose upper bound
// (twoKc * ext_coord + group pot max) exceeds mx_est - TH_SKIP for ANY lane.
// pmax[32]: group max of pots; eptr[32]: group extreme coord (hi if twoKc>=0).
__device__ __forceinline__ float guarded_sum(const float2* __restrict__ arr,
                                             const float* __restrict__ pmax,
                                             const float* __restrict__ eptr,
                                             float twoKc, float mx_est) {
    const float thr = mx_est - TH_SKIP;
    const float4* a4 = reinterpret_cast<const float4*>(arr);
    const float4* pm4 = reinterpret_cast<const float4*>(pmax);
    const float4* ex4 = reinterpret_cast<const float4*>(eptr);
    float sA = 0.f, sB = 0.f;
#pragma unroll
    for (int q = 0; q < 8; ++q) {
        float4 pm = pm4[q];
        float4 ex = ex4[q];
        int g = 4 * q;
        if (__any_sync(0xffffffffu, fmaf(twoKc, ex.x, pm.x) > thr)) {
            float4 u = a4[2 * g], w = a4[2 * g + 1];
            sA += ex2f(fmaf(twoKc, u.x, u.y) - mx_est);
            sB += ex2f(fmaf(twoKc, u.z, u.w) - mx_est);
            sA += ex2f(fmaf(twoKc, w.x, w.y) - mx_est);
            sB += ex2f(fmaf(twoKc, w.z, w.w) - mx_est);
        }
        if (__any_sync(0xffffffffu, fmaf(twoKc, ex.y, pm.y) > thr)) {
            float4 u = a4[2 * g + 2], w = a4[2 * g + 3];
            sA += ex2f(fmaf(twoKc, u.x, u.y) - mx_est);
            sB += ex2f(fmaf(twoKc, u.z, u.w) - mx_est);
            sA += ex2f(fmaf(twoKc, w.x, w.y) - mx_est);
            sB += ex2f(fmaf(twoKc, w.z, w.w) - mx_est);
        }
        if (__any_sync(0xffffffffu, fmaf(twoKc, ex.z, pm.z) > thr)) {
            float4 u = a4[2 * g + 4], w = a4[2 * g + 5];
            sA += ex2f(fmaf(twoKc, u.x, u.y) - mx_est);
            sB += ex2f(fmaf(twoKc, u.z, u.w) - mx_est);
            sA += ex2f(fmaf(twoKc, w.x, w.y) - mx_est);
            sB += ex2f(fmaf(twoKc, w.z, w.w) - mx_est);
        }
        if (__any_sync(0xffffffffu, fmaf(twoKc, ex.w, pm.w) > thr)) {
            float4 u = a4[2 * g + 6], w = a4[2 * g + 7];
            sA += ex2f(fmaf(twoKc, u.x, u.y) - mx_est);
            sB += ex2f(fmaf(twoKc, u.z, u.w) - mx_est);
            sA += ex2f(fmaf(twoKc, w.x, w.y) - mx_est);
            sB += ex2f(fmaf(twoKc, w.z, w.w) - mx_est);
        }
    }
    return sA + sB;
}

__global__ void __launch_bounds__(128) sinkhorn_kernel(const float* __restrict__ X,
                                                       const float* __restrict__ Y) {
    __shared__ __align__(16) float2 sx[DD];   // {sorted x, pot a}
    __shared__ __align__(16) float2 sy[DD];   // {sorted y, pot b}
    __shared__ int ox[DD], oy[DD];            // original indices
    __shared__ __align__(16) float kx[DD], ky[DD];          // sort keys
    __shared__ __align__(16) float apx[32], bpx[32];        // group pot maxes
    __shared__ __align__(16) float xlo[32], xhi[32], ylo[32], yhi[32];

    const int p = blockIdx.x;
    const int t = threadIdx.x;

    kx[t] = X[(size_t)p * DD + t]; ox[t] = t;
    ky[t] = Y[(size_t)p * DD + t]; oy[t] = t;
    __syncthreads();

    // Bitonic sort both (kx,ox) and (ky,oy) ascending; index tiebreak for total order.
    for (int k = 2; k <= DD; k <<= 1) {
        for (int j = k >> 1; j > 0; j >>= 1) {
            int prt = t ^ j;
            bool keep_small = ((t < prt) == ((t & k) == 0));
            float mkx = kx[t], pkx = kx[prt];
            int   mix = ox[t], pix = ox[prt];
            float mky = ky[t], pky = ky[prt];
            int   miy = oy[t], piy = oy[prt];
            __syncthreads();
            bool lessx = (mkx < pkx) || (mkx == pkx && mix < pix);
            bool takex = (lessx == keep_small);
            kx[t] = takex ? mkx : pkx;  ox[t] = takex ? mix : pix;
            bool lessy = (mky < pky) || (mky == pky && miy < piy);
            bool takey = (lessy == keep_small);
            ky[t] = takey ? mky : pky;  oy[t] = takey ? miy : piy;
            __syncthreads();
        }
    }

    const float x = kx[t];
    const float y = ky[t];
    const float twoKx = TWOK * x;
    const float twoKy = TWOK * y;
    float areg = -KCOEF * x * x;
    float breg = -KCOEF * y * y;
    sx[t] = make_float2(x, areg);
    sy[t] = make_float2(y, breg);
    if (t < 32) {
        float x0 = kx[4 * t], x1 = kx[4 * t + 1], x2 = kx[4 * t + 2], x3 = kx[4 * t + 3];
        float y0 = ky[4 * t], y1 = ky[4 * t + 1], y2 = ky[4 * t + 2], y3 = ky[4 * t + 3];
        xlo[t] = x0; xhi[t] = x3;
        ylo[t] = y0; yhi[t] = y3;
        // Initial group pot maxes: pot = -K c^2 -> max = -K min(c^2). Valid for it=0,
        // so the guarded path applies from the first iteration (guard catches tails).
        apx[t] = -KCOEF * fminf(fminf(x0 * x0, x1 * x1), fminf(x2 * x2, x3 * x3));
        bpx[t] = -KCOEF * fminf(fminf(y0 * y0, y1 * y1), fminf(y2 * y2, y3 * y3));
    }
    __syncthreads();

    const float* eyp = (twoKx >= 0.f) ? yhi : ylo;  // extreme y per group for f bound
    const float* exq = (twoKy >= 0.f) ? xhi : xlo;  // extreme x per group for g bound

    for (int it = 0; it < NITER; ++it) {
        // ---- f-update (rows; reduce over sy) ----
        float a_new;
        {
            float mx_est = -7.0f - areg;
            float s = guarded_sum(sy, bpx, eyp, twoKx, mx_est);
            bool bad = !(s >= SMIN && s <= SMAX);
            a_new = -(7.0f + mx_est + lg2f(s));
            if (__any_sync(0xffffffffu, bad)) a_new = lse_full(sy, twoKx);
        }
        areg = a_new;
        float qa = a_new;
        qa = fmaxf(qa, __shfl_xor_sync(0xffffffffu, qa, 1));
        qa = fmaxf(qa, __shfl_xor_sync(0xffffffffu, qa, 2));
        sx[t].y = a_new;
        if ((t & 3) == 0) apx[t >> 2] = qa;
        __syncthreads();

        // ---- g-update (cols; reduce over sx) ----
        float b_new;
        {
            float mx_est = -7.0f - breg;
            float s = guarded_sum(sx, apx, exq, twoKy, mx_est);
            bool bad = !(s >= SMIN && s <= SMAX);
            b_new = -(7.0f + mx_est + lg2f(s));
            if (__any_sync(0xffffffffu, bad)) b_new = lse_full(sx, twoKy);
        }
        breg = b_new;
        float qb = b_new;
        qb = fmaxf(qb, __shfl_xor_sync(0xffffffffu, qb, 1));
        qb = fmaxf(qb, __shfl_xor_sync(0xffffffffu, qb, 2));
        sy[t].y = b_new;
        if ((t & 3) == 0) bpx[t >> 2] = qb;
        __syncthreads();
    }

    // ---- Plan accumulation: thread t = sorted row t; fixed-point atomic adds ----
    // plan_ij = 2^(a_i + b_j + twoK * x_i * y_j); skip groups bounded below 2^PLAN_TH.
    {
        const int oi = ox[t];
        unsigned long long* rowp =
            g_accum + (size_t)(p & (NCOPY - 1)) * (DD * DD) + (size_t)oi * DD;
        const float thr = PLAN_TH - areg;   // fire iff v_j > thr
        const float4* a4 = reinterpret_cast<const float4*>(sy);
        const float4* pm4 = reinterpret_cast<const float4*>(bpx);
        const float4* ex4 = reinterpret_cast<const float4*>(eyp);
#pragma unroll
        for (int q = 0; q < 8; ++q) {
            float4 pm = pm4[q];
            float4 ex = ex4[q];
#pragma unroll
            for (int h = 0; h < 4; ++h) {
                float bnd = (h == 0) ? fmaf(twoKx, ex.x, pm.x)
                          : (h == 1) ? fmaf(twoKx, ex.y, pm.y)
                          : (h == 2) ? fmaf(twoKx, ex.z, pm.z)
                                     : fmaf(twoKx, ex.w, pm.w);
                if (__any_sync(0xffffffffu, bnd > thr)) {
                    int g = 4 * q + h;
                    float4 u = a4[2 * g], w = a4[2 * g + 1];
                    float E0 = fmaf(twoKx, u.x, u.y) + areg;
                    float E1 = fmaf(twoKx, u.z, u.w) + areg;
                    float E2 = fmaf(twoKx, w.x, w.y) + areg;
                    float E3 = fmaf(twoKx, w.z, w.w) + areg;
                    if (E0 > E_TH)
                        atomicAdd(rowp + oy[4 * g + 0],
                                  (unsigned long long)(ex2f(E0) * FIX_SCALE));
                    if (E1 > E_TH)
                        atomicAdd(rowp + oy[4 * g + 1],
                                  (unsigned long long)(ex2f(E1) * FIX_SCALE));
                    if (E2 > E_TH)
                        atomicAdd(rowp + oy[4 * g + 2],
                                  (unsigned long long)(ex2f(E2) * FIX_SCALE));
                    if (E3 > E_TH)
                        atomicAdd(rowp + oy[4 * g + 3],
                                  (unsigned long long)(ex2f(E3) * FIX_SCALE));
                }
            }
        }
    }
}

__global__ void __launch_bounds__(256) zero_accum_kernel() {
    const int idx = blockIdx.x * 256 + threadIdx.x;
    g_accum[idx] = 0ull;
}

// Sum 32 fixed-point copies (exact integer sum -> deterministic), scale, add delta.
__global__ void __launch_bounds__(256) reduce_b_kernel(const float* __restrict__ delta) {
    const int idx = blockIdx.x * 256 + threadIdx.x;
    unsigned long long tot = 0ull;
#pragma unroll
    for (int c = 0; c < NCOPY; ++c) tot += g_accum[(size_t)c * (DD * DD) + idx];
    g_ot[idx] = (float)((double)tot * ((double)OTSCALE / (double)FIX_SCALE)) + delta[idx];
}

// out[p, :] = X[p, :] @ ot  (ot is 64KB, L2 resident; measured-best config)
__global__ void __launch_bounds__(128) gemm_out_kernel(const float* __restrict__ X,
                                                       float* __restrict__ out) {
    __shared__ float xs[DD];
    const int p = blockIdx.x;
    const int t = threadIdx.x;
    xs[t] = X[(size_t)p * DD + t];
    __syncthreads();
    float a0 = 0.f, a1 = 0.f, a2 = 0.f, a3 = 0.f;
#pragma unroll 8
    for (int i = 0; i < DD; i += 4) {
        a0 = fmaf(xs[i + 0], g_ot[(i + 0) * DD + t], a0);
        a1 = fmaf(xs[i + 1], g_ot[(i + 1) * DD + t], a1);
        a2 = fmaf(xs[i + 2], g_ot[(i + 2) * DD + t], a2);
        a3 = fmaf(xs[i + 3], g_ot[(i + 3) * DD + t], a3);
    }
    out[(size_t)p * DD + t] = (a0 + a1) + (a2 + a3);
}

extern "C" void kernel_launch(void* const* d_in, const int* in_sizes, int n_in,
                              void* d_out, int out_size) {
    const float* X = (const float*)d_in[0];      // [8,256,128]
    const float* Y = (const float*)d_in[1];      // [8,256,128]
    const float* delta = (const float*)d_in[2];  // [128,128]
    float* out = (float*)d_out;                  // [8,256,128] float32

    zero_accum_kernel<<<(NCOPY * DD * DD) / 256, 256>>>();
    sinkhorn_kernel<<<NPROB, 128>>>(X, Y);
    reduce_b_kernel<<<(DD * DD) / 256, 256>>>(delta);
    gemm_out_kernel<<<NPROB, 128>>>(X, out);
}